// round 1
// baseline (speedup 1.0000x reference)
#include <cuda_runtime.h>
#include <cuda_bf16.h>
#include <math.h>

#define TOKENS 4096
#define DM     1024
#define DFF    4096
#define HEADS  16
#define DK     64
#define SEQ    2048
#define BATCH  2

// ---------------- scratch (device globals: no allocation) ----------------
__device__ float g_Q[TOKENS * DM];
__device__ float g_K[TOKENS * DM];
__device__ float g_V[TOKENS * DM];
__device__ float g_CTX[TOKENS * DM];
__device__ float g_T1[TOKENS * DM];   // pre-layernorm buffer (reused)
__device__ float g_AO[TOKENS * DM];   // attn_out (post LN1)
__device__ float g_H[TOKENS * DFF];   // FF hidden

__device__ __forceinline__ float gelu_exact(float x) {
    return 0.5f * x * (1.0f + erff(x * 0.70710678118654752f));
}

// ---------------- generic SGEMM: C = A[M,K] @ B[K,N] + bias (+R) (+gelu) --
// EPI: 0 = bias only, 1 = bias + gelu, 2 = bias + residual
template <int EPI>
__global__ __launch_bounds__(256) void gemm_kernel(
    const float* __restrict__ A, const float* __restrict__ B,
    const float* __restrict__ bias, const float* __restrict__ R,
    float* __restrict__ C, int M, int N, int K)
{
    const int BM = 128, BN = 128, BK = 16;
    __shared__ float As[BK][BM];
    __shared__ float Bs[BK][BN];

    int tid = threadIdx.x;
    int tx = tid & 15;        // 0..15 -> 8 cols each
    int ty = tid >> 4;        // 0..15 -> 8 rows each
    int rowBase = blockIdx.y * BM;
    int colBase = blockIdx.x * BN;

    float acc[8][8];
#pragma unroll
    for (int i = 0; i < 8; i++)
#pragma unroll
        for (int j = 0; j < 8; j++) acc[i][j] = 0.0f;

    for (int k0 = 0; k0 < K; k0 += BK) {
        // load A tile (128x16) as 512 float4, store transposed As[k][m]
#pragma unroll
        for (int i = 0; i < 2; i++) {
            int s = tid + i * 256;
            int r = s >> 2;
            int c4 = (s & 3) * 4;
            float4 a = *(const float4*)&A[(size_t)(rowBase + r) * K + k0 + c4];
            As[c4 + 0][r] = a.x;
            As[c4 + 1][r] = a.y;
            As[c4 + 2][r] = a.z;
            As[c4 + 3][r] = a.w;
        }
        // load B tile (16x128) as 512 float4
#pragma unroll
        for (int i = 0; i < 2; i++) {
            int s = tid + i * 256;
            int r = s >> 5;
            int c4 = (s & 31) * 4;
            *(float4*)&Bs[r][c4] = *(const float4*)&B[(size_t)(k0 + r) * N + colBase + c4];
        }
        __syncthreads();

#pragma unroll
        for (int k = 0; k < BK; k++) {
            float ra[8], rb[8];
            *(float4*)&ra[0] = *(float4*)&As[k][ty * 8];
            *(float4*)&ra[4] = *(float4*)&As[k][ty * 8 + 4];
            *(float4*)&rb[0] = *(float4*)&Bs[k][tx * 8];
            *(float4*)&rb[4] = *(float4*)&Bs[k][tx * 8 + 4];
#pragma unroll
            for (int i = 0; i < 8; i++)
#pragma unroll
                for (int j = 0; j < 8; j++)
                    acc[i][j] = fmaf(ra[i], rb[j], acc[i][j]);
        }
        __syncthreads();
    }

    // epilogue
#pragma unroll
    for (int j = 0; j < 8; j += 4) {
        int col = colBase + tx * 8 + j;
        float4 bz = *(const float4*)&bias[col];
#pragma unroll
        for (int i = 0; i < 8; i++) {
            int row = rowBase + ty * 8 + i;
            float4 v;
            v.x = acc[i][j + 0] + bz.x;
            v.y = acc[i][j + 1] + bz.y;
            v.z = acc[i][j + 2] + bz.z;
            v.w = acc[i][j + 3] + bz.w;
            if (EPI == 2) {
                float4 rv = *(const float4*)&R[(size_t)row * N + col];
                v.x += rv.x; v.y += rv.y; v.z += rv.z; v.w += rv.w;
            }
            if (EPI == 1) {
                v.x = gelu_exact(v.x);
                v.y = gelu_exact(v.y);
                v.z = gelu_exact(v.z);
                v.w = gelu_exact(v.w);
            }
            *(float4*)&C[(size_t)row * N + col] = v;
        }
    }
}

// ---------------- flash attention (fp32, online softmax) -----------------
// block: 256 threads; one block per (q_tile=64 rows, head, batch)
// thread t: row r = t/4, group c = t%4.
//   S phase: owns columns j = c + 4*jj (jj 0..15)   [conflict-free Ks reads]
//   O phase: owns dims    d = c*16 + jj             [float4 Vs reads/stores]
__global__ __launch_bounds__(256) void attn_kernel(
    const float* __restrict__ Q, const float* __restrict__ K,
    const float* __restrict__ V, const unsigned char* __restrict__ mask,
    float* __restrict__ CTX)
{
    const int P = 68;  // smem row pitch (floats), 16B-aligned rows
    extern __shared__ float sm[];
    float* Qs = sm;                // 64 * P
    float* Ks = sm + 64 * P;
    float* Vs = sm + 2 * 64 * P;
    float* Ps = sm + 3 * 64 * P;

    int tid = threadIdx.x;
    int c = tid & 3;
    int r = tid >> 2;
    int q0 = blockIdx.x * 64;
    int h  = blockIdx.y;
    int b  = blockIdx.z;
    const float scale = 0.125f;  // 1/sqrt(64)

    // load Q tile (64 x 64) into smem
    const float* Qbase = Q + ((size_t)(b * SEQ + q0)) * DM + h * DK;
#pragma unroll
    for (int i = 0; i < 4; i++) {
        int s = tid + i * 256;
        int rr = s >> 4;
        int c4 = (s & 15) * 4;
        *(float4*)&Qs[rr * P + c4] = *(const float4*)&Qbase[(size_t)rr * DM + c4];
    }

    float o[16];
#pragma unroll
    for (int i = 0; i < 16; i++) o[i] = 0.0f;
    float m_run = -1e30f, l_run = 0.0f;

    const unsigned char* mrow = mask + ((size_t)b * SEQ + (q0 + r)) * SEQ;

    for (int kv0 = 0; kv0 < SEQ; kv0 += 64) {
        __syncthreads();  // protect smem reuse (also covers Q-load on iter 0)
        const float* Kbase = K + ((size_t)(b * SEQ + kv0)) * DM + h * DK;
        const float* Vbase = V + ((size_t)(b * SEQ + kv0)) * DM + h * DK;
#pragma unroll
        for (int i = 0; i < 4; i++) {
            int s = tid + i * 256;
            int rr = s >> 4;
            int c4 = (s & 15) * 4;
            *(float4*)&Ks[rr * P + c4] = *(const float4*)&Kbase[(size_t)rr * DM + c4];
            *(float4*)&Vs[rr * P + c4] = *(const float4*)&Vbase[(size_t)rr * DM + c4];
        }
        __syncthreads();

        // ---- S = Q K^T (thread owns j = c + 4*jj) ----
        float sv[16];
#pragma unroll
        for (int jj = 0; jj < 16; jj++) sv[jj] = 0.0f;
#pragma unroll
        for (int k4 = 0; k4 < 64; k4 += 4) {
            float4 q4 = *(const float4*)&Qs[r * P + k4];
#pragma unroll
            for (int jj = 0; jj < 16; jj++) {
                float4 kv = *(const float4*)&Ks[(c + 4 * jj) * P + k4];
                sv[jj] = fmaf(q4.x, kv.x, sv[jj]);
                sv[jj] = fmaf(q4.y, kv.y, sv[jj]);
                sv[jj] = fmaf(q4.z, kv.z, sv[jj]);
                sv[jj] = fmaf(q4.w, kv.w, sv[jj]);
            }
        }

        // ---- masked scale + online softmax update ----
        float mloc = -1e30f;
#pragma unroll
        for (int jj = 0; jj < 16; jj++) {
            float x = sv[jj] * scale;
            if (mrow[kv0 + c + 4 * jj]) x = -1e9f;
            sv[jj] = x;
            mloc = fmaxf(mloc, x);
        }
        mloc = fmaxf(mloc, __shfl_xor_sync(0xffffffffu, mloc, 1));
        mloc = fmaxf(mloc, __shfl_xor_sync(0xffffffffu, mloc, 2));
        float m_new = fmaxf(m_run, mloc);
        float corr = __expf(m_run - m_new);
        float lsum = 0.0f;
#pragma unroll
        for (int jj = 0; jj < 16; jj++) {
            float p = __expf(sv[jj] - m_new);
            sv[jj] = p;
            lsum += p;
        }
        lsum += __shfl_xor_sync(0xffffffffu, lsum, 1);
        lsum += __shfl_xor_sync(0xffffffffu, lsum, 2);
        l_run = l_run * corr + lsum;
        m_run = m_new;
#pragma unroll
        for (int i = 0; i < 16; i++) o[i] *= corr;

        // stash P into smem (row r owned by its 4 lanes -> warp-local)
#pragma unroll
        for (int jj = 0; jj < 16; jj++)
            Ps[r * P + c + 4 * jj] = sv[jj];
        __syncwarp();

        // ---- O += P @ V (thread owns d = c*16 + jj) ----
#pragma unroll 8
        for (int j = 0; j < 64; j++) {
            float p = Ps[r * P + j];
#pragma unroll
            for (int jj4 = 0; jj4 < 16; jj4 += 4) {
                float4 vv = *(const float4*)&Vs[j * P + c * 16 + jj4];
                o[jj4 + 0] = fmaf(p, vv.x, o[jj4 + 0]);
                o[jj4 + 1] = fmaf(p, vv.y, o[jj4 + 1]);
                o[jj4 + 2] = fmaf(p, vv.z, o[jj4 + 2]);
                o[jj4 + 3] = fmaf(p, vv.w, o[jj4 + 3]);
            }
        }
        __syncwarp();
    }

    float inv = 1.0f / l_run;
    float* out = CTX + ((size_t)(b * SEQ + q0 + r)) * DM + h * DK + c * 16;
#pragma unroll
    for (int jj4 = 0; jj4 < 16; jj4 += 4) {
        float4 v;
        v.x = o[jj4 + 0] * inv;
        v.y = o[jj4 + 1] * inv;
        v.z = o[jj4 + 2] * inv;
        v.w = o[jj4 + 3] * inv;
        *(float4*)&out[jj4] = v;
    }
}

// ---------------- layernorm over last dim (1024), biased var --------------
__global__ __launch_bounds__(256) void layernorm_kernel(
    const float* __restrict__ X, const float* __restrict__ g,
    const float* __restrict__ bt, float* __restrict__ out)
{
    __shared__ float sh_s[8], sh_ss[8], sh_mean, sh_rstd;
    int row = blockIdx.x;
    int tid = threadIdx.x;
    const float* x = X + (size_t)row * DM;
    float4 xv = *(const float4*)&x[tid * 4];
    float s  = xv.x + xv.y + xv.z + xv.w;
    float ss = xv.x * xv.x + xv.y * xv.y + xv.z * xv.z + xv.w * xv.w;
#pragma unroll
    for (int off = 16; off; off >>= 1) {
        s  += __shfl_xor_sync(0xffffffffu, s, off);
        ss += __shfl_xor_sync(0xffffffffu, ss, off);
    }
    int wid = tid >> 5, lane = tid & 31;
    if (lane == 0) { sh_s[wid] = s; sh_ss[wid] = ss; }
    __syncthreads();
    if (wid == 0) {
        float s2  = (lane < 8) ? sh_s[lane]  : 0.0f;
        float ss2 = (lane < 8) ? sh_ss[lane] : 0.0f;
#pragma unroll
        for (int off = 4; off; off >>= 1) {
            s2  += __shfl_xor_sync(0xffffffffu, s2, off);
            ss2 += __shfl_xor_sync(0xffffffffu, ss2, off);
        }
        if (lane == 0) {
            float mean = s2 * (1.0f / DM);
            float var  = ss2 * (1.0f / DM) - mean * mean;
            sh_mean = mean;
            sh_rstd = rsqrtf(var + 1e-5f);
        }
    }
    __syncthreads();
    float mean = sh_mean, rstd = sh_rstd;
    float4 gv = *(const float4*)&g[tid * 4];
    float4 bv = *(const float4*)&bt[tid * 4];
    float4 ov;
    ov.x = (xv.x - mean) * rstd * gv.x + bv.x;
    ov.y = (xv.y - mean) * rstd * gv.y + bv.y;
    ov.z = (xv.z - mean) * rstd * gv.z + bv.z;
    ov.w = (xv.w - mean) * rstd * gv.w + bv.w;
    *(float4*)&out[(size_t)row * DM + tid * 4] = ov;
}

// -------------------------------- host -----------------------------------
extern "C" void kernel_launch(void* const* d_in, const int* in_sizes, int n_in,
                              void* d_out, int out_size)
{
    const float* X    = (const float*)d_in[0];
    const unsigned char* mask = (const unsigned char*)d_in[1];
    const float* Wq  = (const float*)d_in[2];
    const float* bq  = (const float*)d_in[3];
    const float* Wk  = (const float*)d_in[4];
    const float* bk  = (const float*)d_in[5];
    const float* Wv  = (const float*)d_in[6];
    const float* bv  = (const float*)d_in[7];
    const float* Wo  = (const float*)d_in[8];
    const float* bo  = (const float*)d_in[9];
    const float* g1  = (const float*)d_in[10];
    const float* b1  = (const float*)d_in[11];
    const float* W1  = (const float*)d_in[12];
    const float* bf1 = (const float*)d_in[13];
    const float* W2  = (const float*)d_in[14];
    const float* bf2 = (const float*)d_in[15];
    const float* g2  = (const float*)d_in[16];
    const float* b2  = (const float*)d_in[17];
    float* out = (float*)d_out;

    float *Qp, *Kp, *Vp, *CTXp, *T1p, *AOp, *Hp;
    cudaGetSymbolAddress((void**)&Qp,   g_Q);
    cudaGetSymbolAddress((void**)&Kp,   g_K);
    cudaGetSymbolAddress((void**)&Vp,   g_V);
    cudaGetSymbolAddress((void**)&CTXp, g_CTX);
    cudaGetSymbolAddress((void**)&T1p,  g_T1);
    cudaGetSymbolAddress((void**)&AOp,  g_AO);
    cudaGetSymbolAddress((void**)&Hp,   g_H);

    const int attn_smem = 4 * 64 * 68 * (int)sizeof(float);  // 69632 B
    cudaFuncSetAttribute(attn_kernel,
                         cudaFuncAttributeMaxDynamicSharedMemorySize, attn_smem);

    dim3 gproj(DM / 128, TOKENS / 128);     // (8, 32)
    dim3 gff1(DFF / 128, TOKENS / 128);     // (32, 32)

    // QKV projections
    gemm_kernel<0><<<gproj, 256>>>(X, Wq, bq, nullptr, Qp, TOKENS, DM, DM);
    gemm_kernel<0><<<gproj, 256>>>(X, Wk, bk, nullptr, Kp, TOKENS, DM, DM);
    gemm_kernel<0><<<gproj, 256>>>(X, Wv, bv, nullptr, Vp, TOKENS, DM, DM);

    // attention
    dim3 gattn(SEQ / 64, HEADS, BATCH);     // (32, 16, 2)
    attn_kernel<<<gattn, 256, attn_smem>>>(Qp, Kp, Vp, mask, CTXp);

    // output projection + residual, then LN1
    gemm_kernel<2><<<gproj, 256>>>(CTXp, Wo, bo, X, T1p, TOKENS, DM, DM);
    layernorm_kernel<<<TOKENS, 256>>>(T1p, g1, b1, AOp);

    // FF1 + gelu
    gemm_kernel<1><<<gff1, 256>>>(AOp, W1, bf1, nullptr, Hp, TOKENS, DFF, DM);

    // FF2 + residual, then LN2 -> out
    gemm_kernel<2><<<gproj, 256>>>(Hp, W2, bf2, AOp, T1p, TOKENS, DM, DFF);
    layernorm_kernel<<<TOKENS, 256>>>(T1p, g2, b2, out);
}